// round 1
// baseline (speedup 1.0000x reference)
#include <cuda_runtime.h>
#include <math.h>

#define NMAX 100000
#define EMAX 1600000
#define ETOTMAX (EMAX + NMAX)
#define NEG_SLOPE 0.2f
#define LN_EPS 1e-5f

// ---------------- scratch (device globals; no allocation) ----------------
__device__ float g_xc[NMAX * 72];        // concat(x, temporal) for layer 1
__device__ float g_h[NMAX * 64];         // per-layer linear output (reused)
__device__ float g_x1[NMAX * 64];        // layer-1 output (input to layer 2)
__device__ float g_agg[NMAX * 64];       // GAT aggregation buffer (reused)
__device__ float g_s[NMAX * 4];          // per-node src attention logits
__device__ float g_d[NMAX * 4];          // per-node dst attention logits
__device__ float g_m[NMAX * 4];          // segment max
__device__ float g_z[NMAX * 4];          // segment sum
__device__ float g_w[ETOTMAX * 4];       // per-edge unnormalized weights
__device__ float g_gacc[64];             // column sums for global mean

// ---------------- helpers ----------------
__device__ __forceinline__ void atomicMaxF(float* addr, float v) {
    // sign trick: works given init = -inf
    if (v >= 0.0f) atomicMax((int*)addr, __float_as_int(v));
    else atomicMin((unsigned int*)addr, (unsigned int)__float_as_int(v));
}

__device__ __forceinline__ void edge_nodes(const int* __restrict__ ei, int E, long e,
                                           int& s, int& d) {
    if (e < E) { s = ei[e]; d = ei[E + e]; }
    else       { s = d = (int)(e - E); }   // self loop
}

__device__ __forceinline__ float lrelu(float v) {
    return v > 0.0f ? v : NEG_SLOPE * v;
}

// ---------------- fill ----------------
__global__ void fillf(float* p, float v, int n) {
    int i = blockIdx.x * blockDim.x + threadIdx.x;
    if (i < n) p[i] = v;
}

// ---------------- temporal encoder + concat ----------------
__global__ void build_xc(const float* __restrict__ x, const float* __restrict__ tf,
                         const float* __restrict__ Wt, const float* __restrict__ bt,
                         float* __restrict__ xc, int n) {
    int tot = n * 72;
    for (int i = blockIdx.x * blockDim.x + threadIdx.x; i < tot;
         i += gridDim.x * blockDim.x) {
        int node = i / 72, c = i % 72;
        float v;
        if (c < 56) v = x[(long)node * 56 + c];
        else {
            float t = tf[node] * Wt[c - 56] + bt[c - 56];
            v = t > 0.0f ? t : 0.0f;
        }
        xc[i] = v;
    }
}

// ---------------- fused linear + attention logits ----------------
// block = 256 threads = 4 nodes x 64 output cols. W staged in smem.
__global__ void lin_att(const float* __restrict__ in, int in_dim,
                        const float* __restrict__ W,
                        const float* __restrict__ a_src, const float* __restrict__ a_dst,
                        float* __restrict__ h_out, float* __restrict__ s_out,
                        float* __restrict__ d_out_, int n) {
    __shared__ float sW[72 * 64];
    __shared__ float sx[4 * 72];
    __shared__ float sas[64], sad[64];
    int tid = threadIdx.x;
    for (int i = tid; i < in_dim * 64; i += 256) sW[i] = W[i];
    if (tid < 64) { sas[tid] = a_src[tid]; sad[tid] = a_dst[tid]; }
    __syncthreads();

    int lane = tid & 31;
    int node_local = tid >> 6;   // 0..3
    int j = tid & 63;            // output column

    for (int g0 = blockIdx.x * 4; g0 < n; g0 += gridDim.x * 4) {
        __syncthreads();
        for (int i = tid; i < 4 * in_dim; i += 256) {
            int nl = i / in_dim, c = i % in_dim;
            int node = g0 + nl;
            sx[nl * 72 + c] = (node < n) ? in[(long)node * in_dim + c] : 0.0f;
        }
        __syncthreads();
        int node = g0 + node_local;
        if (node < n) {
            const float* xr = &sx[node_local * 72];
            float acc = 0.0f;
#pragma unroll 8
            for (int k = 0; k < in_dim; k++) acc = fmaf(xr[k], sW[k * 64 + j], acc);
            h_out[(long)node * 64 + j] = acc;
            float ps = acc * sas[j];
            float pd = acc * sad[j];
#pragma unroll
            for (int off = 8; off; off >>= 1) {
                ps += __shfl_down_sync(0xffffffffu, ps, off, 16);
                pd += __shfl_down_sync(0xffffffffu, pd, off, 16);
            }
            if ((lane & 15) == 0) {
                int head = j >> 4;
                s_out[node * 4 + head] = ps;
                d_out_[node * 4 + head] = pd;
            }
        }
    }
}

// ---------------- edge pass 1: segment max ----------------
__global__ void edge_max(const int* __restrict__ ei, int E, int etot,
                         const float* __restrict__ s_, const float* __restrict__ d_,
                         float* __restrict__ m_) {
    long e = (long)blockIdx.x * blockDim.x + threadIdx.x;
    if (e >= etot) return;
    int s, d; edge_nodes(ei, E, e, s, d);
    float4 ss = *(const float4*)&s_[s * 4];
    float4 dd = *(const float4*)&d_[d * 4];
    atomicMaxF(&m_[d * 4 + 0], lrelu(ss.x + dd.x));
    atomicMaxF(&m_[d * 4 + 1], lrelu(ss.y + dd.y));
    atomicMaxF(&m_[d * 4 + 2], lrelu(ss.z + dd.z));
    atomicMaxF(&m_[d * 4 + 3], lrelu(ss.w + dd.w));
}

// ---------------- edge pass 2: exp + segment sum ----------------
__global__ void edge_expsum(const int* __restrict__ ei, int E, int etot,
                            const float* __restrict__ s_, const float* __restrict__ d_,
                            const float* __restrict__ m_,
                            float* __restrict__ w_, float* __restrict__ z_) {
    long e = (long)blockIdx.x * blockDim.x + threadIdx.x;
    if (e >= etot) return;
    int s, d; edge_nodes(ei, E, e, s, d);
    float4 ss = *(const float4*)&s_[s * 4];
    float4 dd = *(const float4*)&d_[d * 4];
    float4 mm = *(const float4*)&m_[d * 4];
    float4 w;
    w.x = __expf(lrelu(ss.x + dd.x) - mm.x);
    w.y = __expf(lrelu(ss.y + dd.y) - mm.y);
    w.z = __expf(lrelu(ss.z + dd.z) - mm.z);
    w.w = __expf(lrelu(ss.w + dd.w) - mm.w);
    *(float4*)&w_[e * 4] = w;
    atomicAdd(&z_[d * 4 + 0], w.x);
    atomicAdd(&z_[d * 4 + 1], w.y);
    atomicAdd(&z_[d * 4 + 2], w.z);
    atomicAdd(&z_[d * 4 + 3], w.w);
}

// ---------------- edge pass 3: weighted aggregation (warp per edge) ----------------
__global__ void edge_aggr(const int* __restrict__ ei, int E, int etot,
                          const float* __restrict__ w_, const float* __restrict__ z_,
                          const float* __restrict__ h_, float* __restrict__ agg_) {
    int lane = threadIdx.x & 31;
    long e = (long)blockIdx.x * (blockDim.x >> 5) + (threadIdx.x >> 5);
    if (e >= etot) return;
    int s, d; edge_nodes(ei, E, e, s, d);
    int head = lane >> 3;   // 8 lanes (16 cols) per head
    float alpha = w_[e * 4 + head] / (z_[d * 4 + head] + 1e-16f);
    float2 hv = *(const float2*)&h_[(long)s * 64 + lane * 2];
    atomicAdd(&agg_[(long)d * 64 + lane * 2 + 0], alpha * hv.x);
    atomicAdd(&agg_[(long)d * 64 + lane * 2 + 1], alpha * hv.y);
}

// ---------------- bias + LayerNorm + ReLU (warp per node) ----------------
__global__ void ln_relu(const float* __restrict__ agg_, const float* __restrict__ b,
                        const float* __restrict__ gma, const float* __restrict__ bta,
                        float* __restrict__ out, int n) {
    int lane = threadIdx.x & 31;
    int node = blockIdx.x * (blockDim.x >> 5) + (threadIdx.x >> 5);
    if (node >= n) return;
    float2 v = *(const float2*)&agg_[(long)node * 64 + lane * 2];
    v.x += b[lane * 2];
    v.y += b[lane * 2 + 1];
    float sum = v.x + v.y;
    float sq  = v.x * v.x + v.y * v.y;
#pragma unroll
    for (int off = 16; off; off >>= 1) {
        sum += __shfl_xor_sync(0xffffffffu, sum, off);
        sq  += __shfl_xor_sync(0xffffffffu, sq, off);
    }
    float mean = sum * (1.0f / 64.0f);
    float var  = sq * (1.0f / 64.0f) - mean * mean;
    float inv  = rsqrtf(var + LN_EPS);
    float2 o;
    o.x = (v.x - mean) * inv * gma[lane * 2]     + bta[lane * 2];
    o.y = (v.y - mean) * inv * gma[lane * 2 + 1] + bta[lane * 2 + 1];
    o.x = o.x > 0.0f ? o.x : 0.0f;
    o.y = o.y > 0.0f ? o.y : 0.0f;
    *(float2*)&out[(long)node * 64 + lane * 2] = o;
}

// ---------------- global mean (column sums) ----------------
__global__ void colsum(const float* __restrict__ x2, int n, float* __restrict__ acc) {
    int col = threadIdx.x & 63;
    int rowgrp = threadIdx.x >> 6;  // 0..3
    float s = 0.0f;
    for (int r = blockIdx.x * 4 + rowgrp; r < n; r += gridDim.x * 4)
        s += x2[(long)r * 64 + col];
    __shared__ float sm[256];
    sm[threadIdx.x] = s;
    __syncthreads();
    if (threadIdx.x < 64) {
        float t = sm[threadIdx.x] + sm[threadIdx.x + 64] +
                  sm[threadIdx.x + 128] + sm[threadIdx.x + 192];
        atomicAdd(&acc[threadIdx.x], t);
    }
}

// ---------------- final MLP on mean-pooled embedding ----------------
__global__ void final_mlp(const float* __restrict__ acc, int n,
                          const float* __restrict__ Wp1, const float* __restrict__ bp1,
                          const float* __restrict__ Wp2, const float* __restrict__ bp2,
                          float* __restrict__ out) {
    __shared__ float gein[64], hid[64];
    int t = threadIdx.x;  // 64 threads
    gein[t] = acc[t] / (float)n;
    __syncthreads();
    float a = bp1[t];
#pragma unroll
    for (int k = 0; k < 64; k++) a = fmaf(gein[k], Wp1[k * 64 + t], a);
    hid[t] = a > 0.0f ? a : 0.0f;
    __syncthreads();
    float o = bp2[t];
#pragma unroll
    for (int k = 0; k < 64; k++) o = fmaf(hid[k], Wp2[k * 64 + t], o);
    out[t] = o;
}

// ---------------- host launch ----------------
extern "C" void kernel_launch(void* const* d_in, const int* in_sizes, int n_in,
                              void* d_out, int out_size) {
    const float* x   = (const float*)d_in[0];
    const float* tf  = (const float*)d_in[1];
    const int*   ei  = (const int*)d_in[2];
    const float* Wt  = (const float*)d_in[3];
    const float* bt  = (const float*)d_in[4];
    const float* W1  = (const float*)d_in[5];
    const float* as1 = (const float*)d_in[6];
    const float* ad1 = (const float*)d_in[7];
    const float* b1  = (const float*)d_in[8];
    const float* g1  = (const float*)d_in[9];
    const float* be1 = (const float*)d_in[10];
    const float* W2  = (const float*)d_in[11];
    const float* as2 = (const float*)d_in[12];
    const float* ad2 = (const float*)d_in[13];
    const float* b2  = (const float*)d_in[14];
    const float* g2  = (const float*)d_in[15];
    const float* be2 = (const float*)d_in[16];
    const float* Wp1 = (const float*)d_in[17];
    const float* bp1 = (const float*)d_in[18];
    const float* Wp2 = (const float*)d_in[19];
    const float* bp2 = (const float*)d_in[20];

    int n    = in_sizes[0] / 56;
    int E    = in_sizes[2] / 2;
    int etot = E + n;

    float* out = (float*)d_out;
    float* x2  = out;              // [n, 64]
    float* ge  = out + (long)n * 64;

    float *xc, *h, *x1, *agg, *s, *d, *m, *z, *w, *gacc;
    cudaGetSymbolAddress((void**)&xc,  g_xc);
    cudaGetSymbolAddress((void**)&h,   g_h);
    cudaGetSymbolAddress((void**)&x1,  g_x1);
    cudaGetSymbolAddress((void**)&agg, g_agg);
    cudaGetSymbolAddress((void**)&s,   g_s);
    cudaGetSymbolAddress((void**)&d,   g_d);
    cudaGetSymbolAddress((void**)&m,   g_m);
    cudaGetSymbolAddress((void**)&z,   g_z);
    cudaGetSymbolAddress((void**)&w,   g_w);
    cudaGetSymbolAddress((void**)&gacc, g_gacc);

    const int TB = 256;
    int eb  = (etot + TB - 1) / TB;          // thread-per-edge blocks
    int ewb = (etot + 7) / 8;                // warp-per-edge blocks
    int nwb = (n + 7) / 8;                   // warp-per-node blocks

    // ---- stage 0: temporal concat ----
    build_xc<<<2048, TB>>>(x, tf, Wt, bt, xc, n);

    // ---- layer 1 ----
    lin_att<<<2048, TB>>>(xc, 72, W1, as1, ad1, h, s, d, n);
    fillf<<<(n * 4 + TB - 1) / TB, TB>>>(m, -INFINITY, n * 4);
    fillf<<<(n * 4 + TB - 1) / TB, TB>>>(z, 0.0f, n * 4);
    fillf<<<(n * 64 + TB - 1) / TB, TB>>>(agg, 0.0f, n * 64);
    edge_max<<<eb, TB>>>(ei, E, etot, s, d, m);
    edge_expsum<<<eb, TB>>>(ei, E, etot, s, d, m, w, z);
    edge_aggr<<<ewb, TB>>>(ei, E, etot, w, z, h, agg);
    ln_relu<<<nwb, TB>>>(agg, b1, g1, be1, x1, n);

    // ---- layer 2 ----
    lin_att<<<2048, TB>>>(x1, 64, W2, as2, ad2, h, s, d, n);
    fillf<<<(n * 4 + TB - 1) / TB, TB>>>(m, -INFINITY, n * 4);
    fillf<<<(n * 4 + TB - 1) / TB, TB>>>(z, 0.0f, n * 4);
    fillf<<<(n * 64 + TB - 1) / TB, TB>>>(agg, 0.0f, n * 64);
    edge_max<<<eb, TB>>>(ei, E, etot, s, d, m);
    edge_expsum<<<eb, TB>>>(ei, E, etot, s, d, m, w, z);
    edge_aggr<<<ewb, TB>>>(ei, E, etot, w, z, h, agg);
    ln_relu<<<nwb, TB>>>(agg, b2, g2, be2, x2, n);

    // ---- global mean pool + MLP ----
    fillf<<<1, 64>>>(gacc, 0.0f, 64);
    colsum<<<1024, TB>>>(x2, n, gacc);
    final_mlp<<<1, 64>>>(gacc, n, Wp1, bp1, Wp2, bp2, ge);
}

// round 2
// speedup vs baseline: 1.7399x; 1.7399x over previous
#include <cuda_runtime.h>
#include <math.h>

#define NMAX 100000
#define EMAX 1600000
#define ETOTMAX (EMAX + NMAX)
#define NEG_SLOPE 0.2f
#define LN_EPS 1e-5f

// ---------------- scratch (device globals; no allocation) ----------------
__device__ float g_xc[NMAX * 72];        // concat(x, temporal) for layer 1
__device__ float g_h[NMAX * 64];         // per-layer linear output (reused)
__device__ float g_x1[NMAX * 64];        // layer-1 output (input to layer 2)
__device__ float g_agg[NMAX * 64];       // GAT aggregation buffer (reused)
__device__ float g_s[NMAX * 4];          // per-node src attention logits
__device__ float g_d[NMAX * 4];          // per-node dst attention logits
__device__ float g_z[NMAX * 4];          // segment sum of exp-logits
__device__ float g_gacc[64];             // column sums for global mean

// ---------------- helpers ----------------
__device__ __forceinline__ void edge_nodes(const int* __restrict__ ei, int E, long e,
                                           int& s, int& d) {
    if (e < E) { s = ei[e]; d = ei[E + e]; }
    else       { s = d = (int)(e - E); }   // self loop
}

__device__ __forceinline__ float lrelu(float v) {
    return v > 0.0f ? v : NEG_SLOPE * v;
}

// ---------------- fill ----------------
__global__ void fillf(float* p, float v, int n) {
    int i = blockIdx.x * blockDim.x + threadIdx.x;
    if (i < n) p[i] = v;
}

// ---------------- temporal encoder + concat ----------------
__global__ void build_xc(const float* __restrict__ x, const float* __restrict__ tf,
                         const float* __restrict__ Wt, const float* __restrict__ bt,
                         float* __restrict__ xc, int n) {
    int tot = n * 72;
    for (int i = blockIdx.x * blockDim.x + threadIdx.x; i < tot;
         i += gridDim.x * blockDim.x) {
        int node = i / 72, c = i % 72;
        float v;
        if (c < 56) v = x[(long)node * 56 + c];
        else {
            float t = tf[node] * Wt[c - 56] + bt[c - 56];
            v = t > 0.0f ? t : 0.0f;
        }
        xc[i] = v;
    }
}

// ---------------- fused linear + attention logits ----------------
// block = 256 threads = 4 nodes x 64 output cols. W staged in smem.
__global__ void lin_att(const float* __restrict__ in, int in_dim,
                        const float* __restrict__ W,
                        const float* __restrict__ a_src, const float* __restrict__ a_dst,
                        float* __restrict__ h_out, float* __restrict__ s_out,
                        float* __restrict__ d_out_, int n) {
    __shared__ float sW[72 * 64];
    __shared__ float sx[4 * 72];
    __shared__ float sas[64], sad[64];
    int tid = threadIdx.x;
    for (int i = tid; i < in_dim * 64; i += 256) sW[i] = W[i];
    if (tid < 64) { sas[tid] = a_src[tid]; sad[tid] = a_dst[tid]; }
    __syncthreads();

    int lane = tid & 31;
    int node_local = tid >> 6;   // 0..3
    int j = tid & 63;            // output column

    for (int g0 = blockIdx.x * 4; g0 < n; g0 += gridDim.x * 4) {
        __syncthreads();
        for (int i = tid; i < 4 * in_dim; i += 256) {
            int nl = i / in_dim, c = i % in_dim;
            int node = g0 + nl;
            sx[nl * 72 + c] = (node < n) ? in[(long)node * in_dim + c] : 0.0f;
        }
        __syncthreads();
        int node = g0 + node_local;
        if (node < n) {
            const float* xr = &sx[node_local * 72];
            float acc = 0.0f;
#pragma unroll 8
            for (int k = 0; k < in_dim; k++) acc = fmaf(xr[k], sW[k * 64 + j], acc);
            h_out[(long)node * 64 + j] = acc;
            float ps = acc * sas[j];
            float pd = acc * sad[j];
#pragma unroll
            for (int off = 8; off; off >>= 1) {
                ps += __shfl_down_sync(0xffffffffu, ps, off, 16);
                pd += __shfl_down_sync(0xffffffffu, pd, off, 16);
            }
            if ((lane & 15) == 0) {
                int head = j >> 4;
                s_out[node * 4 + head] = ps;
                d_out_[node * 4 + head] = pd;
            }
        }
    }
}

// ---------------- single fused edge pass ----------------
// half-warp (16 lanes) per edge. Each lane owns 4 consecutive output columns.
// w = exp(leaky_relu(s[src]+d[dst])) per head (max-shift dropped: exactly
// equivalent softmax, magnitudes are O(1)).  Accumulate w*h[src] into agg[dst]
// with a single float4 atomic per lane, and w into z[dst] (one lane per head).
__global__ void edge_fused(const int* __restrict__ ei, int E, int etot,
                           const float* __restrict__ s_, const float* __restrict__ d_,
                           const float* __restrict__ h_,
                           float* __restrict__ agg_, float* __restrict__ z_) {
    int l = threadIdx.x & 15;                       // lane within half-warp
    long e = (long)blockIdx.x * (blockDim.x >> 4) + (threadIdx.x >> 4);
    if (e >= etot) return;
    int s, d; edge_nodes(ei, E, e, s, d);
    int head = l >> 2;
    float w = __expf(lrelu(s_[s * 4 + head] + d_[d * 4 + head]));
    if ((l & 3) == 0) atomicAdd(&z_[d * 4 + head], w);
    float4 hv = *(const float4*)&h_[(long)s * 64 + l * 4];
    float4 v = make_float4(w * hv.x, w * hv.y, w * hv.z, w * hv.w);
    atomicAdd((float4*)&agg_[(long)d * 64 + l * 4], v);
}

// ---------------- normalize + bias + LayerNorm + ReLU (warp per node) ----------------
__global__ void ln_relu(const float* __restrict__ agg_, const float* __restrict__ z_,
                        const float* __restrict__ b,
                        const float* __restrict__ gma, const float* __restrict__ bta,
                        float* __restrict__ out, int n) {
    int lane = threadIdx.x & 31;
    int node = blockIdx.x * (blockDim.x >> 5) + (threadIdx.x >> 5);
    if (node >= n) return;
    int head = lane >> 3;                            // cols lane*2, lane*2+1
    float zinv = 1.0f / (z_[node * 4 + head] + 1e-16f);
    float2 v = *(const float2*)&agg_[(long)node * 64 + lane * 2];
    v.x = v.x * zinv + b[lane * 2];
    v.y = v.y * zinv + b[lane * 2 + 1];
    float sum = v.x + v.y;
    float sq  = v.x * v.x + v.y * v.y;
#pragma unroll
    for (int off = 16; off; off >>= 1) {
        sum += __shfl_xor_sync(0xffffffffu, sum, off);
        sq  += __shfl_xor_sync(0xffffffffu, sq, off);
    }
    float mean = sum * (1.0f / 64.0f);
    float var  = sq * (1.0f / 64.0f) - mean * mean;
    float inv  = rsqrtf(var + LN_EPS);
    float2 o;
    o.x = (v.x - mean) * inv * gma[lane * 2]     + bta[lane * 2];
    o.y = (v.y - mean) * inv * gma[lane * 2 + 1] + bta[lane * 2 + 1];
    o.x = o.x > 0.0f ? o.x : 0.0f;
    o.y = o.y > 0.0f ? o.y : 0.0f;
    *(float2*)&out[(long)node * 64 + lane * 2] = o;
}

// ---------------- global mean (column sums) ----------------
__global__ void colsum(const float* __restrict__ x2, int n, float* __restrict__ acc) {
    int col = threadIdx.x & 63;
    int rowgrp = threadIdx.x >> 6;  // 0..3
    float s = 0.0f;
    for (int r = blockIdx.x * 4 + rowgrp; r < n; r += gridDim.x * 4)
        s += x2[(long)r * 64 + col];
    __shared__ float sm[256];
    sm[threadIdx.x] = s;
    __syncthreads();
    if (threadIdx.x < 64) {
        float t = sm[threadIdx.x] + sm[threadIdx.x + 64] +
                  sm[threadIdx.x + 128] + sm[threadIdx.x + 192];
        atomicAdd(&acc[threadIdx.x], t);
    }
}

// ---------------- final MLP on mean-pooled embedding ----------------
__global__ void final_mlp(const float* __restrict__ acc, int n,
                          const float* __restrict__ Wp1, const float* __restrict__ bp1,
                          const float* __restrict__ Wp2, const float* __restrict__ bp2,
                          float* __restrict__ out) {
    __shared__ float gein[64], hid[64];
    int t = threadIdx.x;  // 64 threads
    gein[t] = acc[t] / (float)n;
    __syncthreads();
    float a = bp1[t];
#pragma unroll
    for (int k = 0; k < 64; k++) a = fmaf(gein[k], Wp1[k * 64 + t], a);
    hid[t] = a > 0.0f ? a : 0.0f;
    __syncthreads();
    float o = bp2[t];
#pragma unroll
    for (int k = 0; k < 64; k++) o = fmaf(hid[k], Wp2[k * 64 + t], o);
    out[t] = o;
}

// ---------------- host launch ----------------
extern "C" void kernel_launch(void* const* d_in, const int* in_sizes, int n_in,
                              void* d_out, int out_size) {
    const float* x   = (const float*)d_in[0];
    const float* tf  = (const float*)d_in[1];
    const int*   ei  = (const int*)d_in[2];
    const float* Wt  = (const float*)d_in[3];
    const float* bt  = (const float*)d_in[4];
    const float* W1  = (const float*)d_in[5];
    const float* as1 = (const float*)d_in[6];
    const float* ad1 = (const float*)d_in[7];
    const float* b1  = (const float*)d_in[8];
    const float* g1  = (const float*)d_in[9];
    const float* be1 = (const float*)d_in[10];
    const float* W2  = (const float*)d_in[11];
    const float* as2 = (const float*)d_in[12];
    const float* ad2 = (const float*)d_in[13];
    const float* b2  = (const float*)d_in[14];
    const float* g2  = (const float*)d_in[15];
    const float* be2 = (const float*)d_in[16];
    const float* Wp1 = (const float*)d_in[17];
    const float* bp1 = (const float*)d_in[18];
    const float* Wp2 = (const float*)d_in[19];
    const float* bp2 = (const float*)d_in[20];

    int n    = in_sizes[0] / 56;
    int E    = in_sizes[2] / 2;
    int etot = E + n;

    float* out = (float*)d_out;
    float* x2  = out;              // [n, 64]
    float* ge  = out + (long)n * 64;

    float *xc, *h, *x1, *agg, *s, *d, *z, *gacc;
    cudaGetSymbolAddress((void**)&xc,  g_xc);
    cudaGetSymbolAddress((void**)&h,   g_h);
    cudaGetSymbolAddress((void**)&x1,  g_x1);
    cudaGetSymbolAddress((void**)&agg, g_agg);
    cudaGetSymbolAddress((void**)&s,   g_s);
    cudaGetSymbolAddress((void**)&d,   g_d);
    cudaGetSymbolAddress((void**)&z,   g_z);
    cudaGetSymbolAddress((void**)&gacc, g_gacc);

    const int TB = 256;
    int ehb = (etot + 15) / 16;              // half-warp-per-edge blocks
    int nwb = (n + 7) / 8;                   // warp-per-node blocks

    // ---- stage 0: temporal concat ----
    build_xc<<<2048, TB>>>(x, tf, Wt, bt, xc, n);

    // ---- layer 1 ----
    lin_att<<<2048, TB>>>(xc, 72, W1, as1, ad1, h, s, d, n);
    fillf<<<(n * 4 + TB - 1) / TB, TB>>>(z, 0.0f, n * 4);
    fillf<<<(n * 64 + TB - 1) / TB, TB>>>(agg, 0.0f, n * 64);
    edge_fused<<<ehb, TB>>>(ei, E, etot, s, d, h, agg, z);
    ln_relu<<<nwb, TB>>>(agg, z, b1, g1, be1, x1, n);

    // ---- layer 2 ----
    lin_att<<<2048, TB>>>(x1, 64, W2, as2, ad2, h, s, d, n);
    fillf<<<(n * 4 + TB - 1) / TB, TB>>>(z, 0.0f, n * 4);
    fillf<<<(n * 64 + TB - 1) / TB, TB>>>(agg, 0.0f, n * 64);
    edge_fused<<<ehb, TB>>>(ei, E, etot, s, d, h, agg, z);
    ln_relu<<<nwb, TB>>>(agg, z, b2, g2, be2, x2, n);

    // ---- global mean pool + MLP ----
    fillf<<<1, 64>>>(gacc, 0.0f, 64);
    colsum<<<1024, TB>>>(x2, n, gacc);
    final_mlp<<<1, 64>>>(gacc, n, Wp1, bp1, Wp2, bp2, ge);
}